// round 2
// baseline (speedup 1.0000x reference)
#include <cuda_runtime.h>
#include <cuda_bf16.h>

#define BB   16
#define TT   128
#define EE   512
#define HH   512
#define G4   2048      // 4*H
#define NLY  4
#define VT   32000
#define NTOK (BB*TT)   // 2048
#define NBLK 128       // recurrent grid (<=148 SMs -> all co-resident)

// ---------------- scratch (device globals; no allocs allowed) ----------------
__device__ float g_x0[NTOK*EE];      // 4MB ping
__device__ float g_x1[NTOK*EE];      // 4MB pong
__device__ float g_xW[NTOK*G4];      // 16MB gate pre-activations
__device__ float g_h [BB*HH];        // current hidden state
__device__ float g_hN[NLY*BB*HH];    // encoder final h per layer
__device__ float g_cN[NLY*BB*HH];    // encoder final c per layer
__device__ volatile unsigned g_bar_gen;
__device__ unsigned g_bar_cnt;

// ---------------- packed f32x2 helpers ----------------
__device__ __forceinline__ void fma2(unsigned long long &acc,
                                     unsigned long long a,
                                     unsigned long long b) {
    asm("fma.rn.f32x2 %0, %1, %2, %0;" : "+l"(acc) : "l"(a), "l"(b));
}
__device__ __forceinline__ unsigned long long dup2(float a) {
    unsigned long long r;
    asm("mov.b64 %0, {%1, %1};" : "=l"(r) : "f"(a));
    return r;
}
__device__ __forceinline__ float lo32(unsigned long long v) {
    return __uint_as_float((unsigned)v);
}
__device__ __forceinline__ float hi32(unsigned long long v) {
    return __uint_as_float((unsigned)(v >> 32));
}

// ---------------- software grid barrier (all NBLK blocks co-resident) ----------------
__device__ __forceinline__ void grid_barrier() {
    __threadfence();
    __syncthreads();
    if (threadIdx.x == 0) {
        unsigned gen = g_bar_gen;
        unsigned old = atomicAdd(&g_bar_cnt, 1u);
        if (old == NBLK - 1) {
            atomicExch(&g_bar_cnt, 0u);
            __threadfence();
            g_bar_gen = gen + 1;
        } else {
            while (g_bar_gen == gen) { __nanosleep(32); }
        }
        __threadfence();
    }
    __syncthreads();
}

// ---------------- embedding gather ----------------
__global__ void embed_kernel(const int* __restrict__ idx,
                             const float* __restrict__ emb,
                             float* __restrict__ out) {
    int row = blockIdx.x;                       // 0..2047 (b*T+t)
    int v   = idx[row];
    const float4* s = (const float4*)(emb + (size_t)v * EE);
    float4*       d = (float4*)(out + (size_t)row * EE);
    d[threadIdx.x] = s[threadIdx.x];            // 128 thr * float4 = 512
}

// ---------------- SGEMM (f32x2): C[M,N] = A[M,512] * W[N,512]^T + bias ----------------
// BM=BN=128, BK=16, 256 threads, 8x8 per thread. M,N multiples of 128, K=512.
__global__ __launch_bounds__(256)
void gemm_bias(const float* __restrict__ A,
               const float* __restrict__ W,
               const float* __restrict__ bias,
               float* __restrict__ C, int N) {
    __shared__ float As[16][132];
    __shared__ float Bs[16][132];
    const int tid = threadIdx.x;
    const int tx = tid & 15, ty = tid >> 4;
    const int n0 = blockIdx.x * 128, m0 = blockIdx.y * 128;

    unsigned long long acc[8][4];
#pragma unroll
    for (int i = 0; i < 8; i++)
#pragma unroll
        for (int j = 0; j < 4; j++) acc[i][j] = 0ull;

    for (int k0 = 0; k0 < 512; k0 += 16) {
#pragma unroll
        for (int i = 0; i < 2; i++) {
            int f4 = tid * 2 + i;               // 0..511
            int m  = f4 >> 2, kq = f4 & 3;
            float4 va = *(const float4*)&A[(size_t)(m0 + m) * 512 + k0 + kq * 4];
            As[kq*4+0][m] = va.x; As[kq*4+1][m] = va.y;
            As[kq*4+2][m] = va.z; As[kq*4+3][m] = va.w;
            float4 vb = *(const float4*)&W[(size_t)(n0 + m) * 512 + k0 + kq * 4];
            Bs[kq*4+0][m] = vb.x; Bs[kq*4+1][m] = vb.y;
            Bs[kq*4+2][m] = vb.z; Bs[kq*4+3][m] = vb.w;
        }
        __syncthreads();
#pragma unroll
        for (int kk = 0; kk < 16; kk++) {
            float4 a0 = *(const float4*)&As[kk][ty * 8];
            float4 a1 = *(const float4*)&As[kk][ty * 8 + 4];
            ulonglong2 b01 = *(const ulonglong2*)&Bs[kk][tx * 8];
            ulonglong2 b23 = *(const ulonglong2*)&Bs[kk][tx * 8 + 4];
            unsigned long long bp[4] = { b01.x, b01.y, b23.x, b23.y };
            float av[8] = { a0.x, a0.y, a0.z, a0.w, a1.x, a1.y, a1.z, a1.w };
#pragma unroll
            for (int i = 0; i < 8; i++) {
                unsigned long long ad = dup2(av[i]);
#pragma unroll
                for (int j = 0; j < 4; j++) fma2(acc[i][j], ad, bp[j]);
            }
        }
        __syncthreads();
    }

    float4 bv0 = *(const float4*)&bias[n0 + tx * 8];
    float4 bv1 = *(const float4*)&bias[n0 + tx * 8 + 4];
    float bvf[8] = { bv0.x, bv0.y, bv0.z, bv0.w, bv1.x, bv1.y, bv1.z, bv1.w };
#pragma unroll
    for (int i = 0; i < 8; i++) {
        int row = m0 + ty * 8 + i;
        float o[8];
#pragma unroll
        for (int j = 0; j < 4; j++) {
            o[2*j]   = lo32(acc[i][j]) + bvf[2*j];
            o[2*j+1] = hi32(acc[i][j]) + bvf[2*j+1];
        }
        *(float4*)&C[(size_t)row * N + n0 + tx * 8]     = make_float4(o[0], o[1], o[2], o[3]);
        *(float4*)&C[(size_t)row * N + n0 + tx * 8 + 4] = make_float4(o[4], o[5], o[6], o[7]);
    }
}

// ---------------- persistent LSTM layer ----------------
// Grid = NBLK(128) blocks x 256 threads. Block bk owns k-slice [bk*4, bk*4+4),
// i.e. 16 Whh rows (4 gates x 4 k), held in REGISTERS for all 128 steps.
// Thread (jj = tid&15, seg = tid>>4): W[jrow(jj), seg*32..seg*32+31] (32 floats).
__device__ __forceinline__ float sigmoidf_(float x) {
    return 1.0f / (1.0f + expf(-x));
}

__global__ __launch_bounds__(256)
void lstm_layer(const float* __restrict__ xW,     // [B*T, 2048]
                const float* __restrict__ Whh,    // [2048, 512]
                float* __restrict__ x_out,        // [B*T, 512]
                const float* __restrict__ h0,     // [B,512] or null->0
                const float* __restrict__ c0,     // [B,512] or null->0
                float* __restrict__ hN,           // [B,512] or null
                float* __restrict__ cN) {
    __shared__ float h_s[BB * HH];          // 32KB
    __shared__ float red[8 * 16 * 17];      // 8.5KB partial sums
    __shared__ float gpre[4][64];           // gate pre-activations
    __shared__ float c_s[4][16];            // cell state (persistent)

    const int tid = threadIdx.x;
    const int bk  = blockIdx.x;
    const int jj  = tid & 15, seg = tid >> 4;
    const int k0  = bk * 4;
    const int jrow = (jj >> 2) * 512 + k0 + (jj & 3);

    // Whh slice -> registers as f32x2 pairs
    unsigned long long w2[16];
    {
        const float* wr = Whh + (size_t)jrow * 512 + seg * 32;
#pragma unroll
        for (int u = 0; u < 16; u++)
            w2[u] = *reinterpret_cast<const unsigned long long*>(wr + u * 2);
    }

    // gather-phase mapping: 256 = 16(b) x 4(kx) x 4(gate)
    const int b2 = tid & 15, kx2 = (tid >> 4) & 3, q2 = tid >> 6;
    const int jjg = q2 * 4 + kx2;
    const int jrg = q2 * 512 + k0 + kx2;

    float h_last = 0.f, c_last = 0.f;
    if (tid < 64) {
        int b = tid & 15, kx = tid >> 4, k = k0 + kx;
        c_s[kx][b] = c0 ? c0[b * HH + k] : 0.f;
        g_h[b * HH + k] = h0 ? h0[b * HH + k] : 0.f;
    }
    grid_barrier();

    for (int t = 0; t < TT; t++) {
        // reload h (L2-coherent) into smem
        const float4* gh4 = (const float4*)g_h;
        float4* hs4 = (float4*)h_s;
#pragma unroll
        for (int u = 0; u < 8; u++)
            hs4[tid + u * 256] = __ldcg(gh4 + tid + u * 256);
        __syncthreads();

        // partial dot: acc[b] = sum_{k in my 32} h[b,k]*W[jrow,k]
        unsigned long long acc[16];
#pragma unroll
        for (int b = 0; b < 16; b++) acc[b] = 0ull;
#pragma unroll
        for (int u = 0; u < 16; u += 2) {
            const unsigned long long wa = w2[u], wb = w2[u + 1];
#pragma unroll
            for (int b = 0; b < 16; b++) {
                ulonglong2 hv = *reinterpret_cast<const ulonglong2*>(
                    &h_s[b * HH + seg * 32 + u * 2]);
                fma2(acc[b], wa, hv.x);
                fma2(acc[b], wb, hv.y);
            }
        }
        // pair-reduce across adjacent segs via shuffle, store 8 partials
#pragma unroll
        for (int b = 0; b < 16; b++) {
            float p = lo32(acc[b]) + hi32(acc[b]);
            p += __shfl_xor_sync(0xffffffffu, p, 16);
            if ((tid & 16) == 0)
                red[((seg >> 1) * 16 + jj) * 17 + b] = p;
        }
        __syncthreads();

        // gather: full dot + xW
        float gv = xW[((size_t)b2 * TT + t) * G4 + jrg];
#pragma unroll
        for (int s = 0; s < 8; s++) gv += red[(s * 16 + jjg) * 17 + b2];
        gpre[q2][kx2 * 16 + b2] = gv;
        __syncthreads();

        // pointwise update (64 threads own the block's 16b x 4k states)
        if (tid < 64) {
            int b = tid & 15, kx = tid >> 4, k = k0 + kx;
            float iv = gpre[0][kx * 16 + b];
            float fv = gpre[1][kx * 16 + b];
            float gg = gpre[2][kx * 16 + b];
            float ov = gpre[3][kx * 16 + b];
            float cold = c_s[kx][b];
            float cn = sigmoidf_(fv) * cold + sigmoidf_(iv) * tanhf(gg);
            float hn = sigmoidf_(ov) * tanhf(cn);
            c_s[kx][b] = cn;
            h_last = hn; c_last = cn;
            g_h[b * HH + k] = hn;
            x_out[((size_t)b * TT + t) * HH + k] = hn;
        }
        grid_barrier();
    }

    if (hN != nullptr && tid < 64) {
        int b = tid & 15, kx = tid >> 4, k = k0 + kx;
        hN[b * HH + k] = h_last;
        cN[b * HH + k] = c_last;
    }
}

// ---------------- host orchestration ----------------
extern "C" void kernel_launch(void* const* d_in, const int* in_sizes, int n_in,
                              void* d_out, int out_size) {
    (void)in_sizes; (void)n_in; (void)out_size;
    const int*   src     = (const int*)  d_in[0];
    const int*   tgt     = (const int*)  d_in[1];
    const float* src_emb = (const float*)d_in[2];
    const float* tgt_emb = (const float*)d_in[3];
    const float* enc_Wih = (const float*)d_in[4];
    const float* enc_Whh = (const float*)d_in[5];
    const float* enc_b   = (const float*)d_in[6];
    const float* dec_Wih = (const float*)d_in[7];
    const float* dec_Whh = (const float*)d_in[8];
    const float* dec_b   = (const float*)d_in[9];
    const float* fc_W    = (const float*)d_in[10];
    const float* fc_b    = (const float*)d_in[11];
    float* out = (float*)d_out;

    float *x0, *x1, *xw, *hN, *cN;
    cudaGetSymbolAddress((void**)&x0, g_x0);
    cudaGetSymbolAddress((void**)&x1, g_x1);
    cudaGetSymbolAddress((void**)&xw, g_xW);
    cudaGetSymbolAddress((void**)&hN, g_hN);
    cudaGetSymbolAddress((void**)&cN, g_cN);

    dim3 ggemm(G4 / 128, NTOK / 128);   // 16 x 16

    // ---- encoder ----
    embed_kernel<<<NTOK, 128>>>(src, src_emb, x0);
    for (int l = 0; l < NLY; l++) {
        const float* xi = (l & 1) ? x1 : x0;
        float*       xo = (l & 1) ? x0 : x1;
        gemm_bias<<<ggemm, 256>>>(xi, enc_Wih + (size_t)l * G4 * EE,
                                  enc_b + l * G4, xw, G4);
        lstm_layer<<<NBLK, 256>>>(xw, enc_Whh + (size_t)l * G4 * HH, xo,
                                  nullptr, nullptr,
                                  hN + l * BB * HH, cN + l * BB * HH);
    }
    // ---- decoder (init from encoder finals) ----
    embed_kernel<<<NTOK, 128>>>(tgt, tgt_emb, x0);
    for (int l = 0; l < NLY; l++) {
        const float* xi = (l & 1) ? x1 : x0;
        float*       xo = (l & 1) ? x0 : x1;
        gemm_bias<<<ggemm, 256>>>(xi, dec_Wih + (size_t)l * G4 * EE,
                                  dec_b + l * G4, xw, G4);
        lstm_layer<<<NBLK, 256>>>(xw, dec_Whh + (size_t)l * G4 * HH, xo,
                                  hN + l * BB * HH, cN + l * BB * HH,
                                  nullptr, nullptr);
    }
    // ---- vocab projection (decoder layer-3 output lands in x0) ----
    gemm_bias<<<dim3(VT / 128, NTOK / 128), 256>>>(x0, fc_W, fc_b, out, VT);
}